// round 1
// baseline (speedup 1.0000x reference)
#include <cuda_runtime.h>

// focal_loss: out = COEF * sum_i ( idx==0 ? log(p) : idx==1 ? log(1-p) : 0 )
// COEF = 0.1 * (1-0.8)^2 = 0.004
// Pure streaming reduction: 128 MiB read, HBM-bound. Two-stage deterministic
// tree reduction (no float atomics), scratch in __device__ global (no allocs).

#define RED_BLOCKS  2048
#define RED_THREADS 256

__device__ float g_partials[RED_BLOCKS];

__device__ __forceinline__ float term_of(float p, int idx) {
    // idx==0 -> log(p); idx==1 -> log(1-p); else log(1)=0. One MUFU per elem.
    float x = (idx == 0) ? p : ((idx == 1) ? (1.0f - p) : 1.0f);
    return __logf(x);
}

__global__ void __launch_bounds__(RED_THREADS)
focal_loss_main(const float* __restrict__ p, const int* __restrict__ idx, int n4) {
    const float4* __restrict__ p4 = reinterpret_cast<const float4*>(p);
    const int4*   __restrict__ i4 = reinterpret_cast<const int4*>(idx);

    float acc = 0.0f;
    int stride = gridDim.x * blockDim.x;
    for (int i = blockIdx.x * blockDim.x + threadIdx.x; i < n4; i += stride) {
        float4 pv = p4[i];
        int4   iv = i4[i];
        acc += term_of(pv.x, iv.x);
        acc += term_of(pv.y, iv.y);
        acc += term_of(pv.z, iv.z);
        acc += term_of(pv.w, iv.w);
    }

    // warp reduce
    #pragma unroll
    for (int o = 16; o > 0; o >>= 1)
        acc += __shfl_down_sync(0xffffffffu, acc, o);

    __shared__ float s[RED_THREADS / 32];
    if ((threadIdx.x & 31) == 0) s[threadIdx.x >> 5] = acc;
    __syncthreads();

    if (threadIdx.x < 32) {
        float v = (threadIdx.x < RED_THREADS / 32) ? s[threadIdx.x] : 0.0f;
        #pragma unroll
        for (int o = 4; o > 0; o >>= 1)
            v += __shfl_down_sync(0xffffffffu, v, o);
        if (threadIdx.x == 0) g_partials[blockIdx.x] = v;
    }
}

__global__ void __launch_bounds__(RED_THREADS)
focal_loss_final(const float* __restrict__ p, const int* __restrict__ idx,
                 int n, int n4, float* __restrict__ out) {
    float acc = 0.0f;
    // fold block partials
    for (int i = threadIdx.x; i < RED_BLOCKS; i += RED_THREADS)
        acc += g_partials[i];
    // scalar tail (n not multiple of 4) — usually empty for N=16M
    for (int i = n4 * 4 + (int)threadIdx.x; i < n; i += RED_THREADS)
        acc += term_of(p[i], idx[i]);

    #pragma unroll
    for (int o = 16; o > 0; o >>= 1)
        acc += __shfl_down_sync(0xffffffffu, acc, o);

    __shared__ float s[RED_THREADS / 32];
    if ((threadIdx.x & 31) == 0) s[threadIdx.x >> 5] = acc;
    __syncthreads();

    if (threadIdx.x < 32) {
        float v = (threadIdx.x < RED_THREADS / 32) ? s[threadIdx.x] : 0.0f;
        #pragma unroll
        for (int o = 4; o > 0; o >>= 1)
            v += __shfl_down_sync(0xffffffffu, v, o);
        if (threadIdx.x == 0)
            out[0] = 0.004f * v;   // COEF = 0.1 * (1-0.8)^2
    }
}

extern "C" void kernel_launch(void* const* d_in, const int* in_sizes, int n_in,
                              void* d_out, int out_size) {
    const float* p   = (const float*)d_in[0];
    const int*   idx = (const int*)d_in[1];
    float* out = (float*)d_out;
    int n  = in_sizes[0];
    int n4 = n >> 2;

    focal_loss_main<<<RED_BLOCKS, RED_THREADS>>>(p, idx, n4);
    focal_loss_final<<<1, RED_THREADS>>>(p, idx, n, n4, out);
}